// round 6
// baseline (speedup 1.0000x reference)
#include <cuda_runtime.h>

#define BB   32
#define SS   512
#define HH   768
#define NC   32
#define MHL  16
#define H4   (HH / 4)       // 192 float4 per row
#define CPL  6              // float4 chunks per lane (192/32)
#define TPB  256            // 8 warps, each handling 2 interleaved rows
#define NCOMB (2 * 11 * 6)  // 132

__device__ float4 g_comb[NCOMB * H4];

__global__ __launch_bounds__(192)
void build_comb_kernel(const float4* __restrict__ tok_type_emb,
                       const float4* __restrict__ match_emb,
                       const float4* __restrict__ type_emb)
{
    const int combo = blockIdx.x;          // 0..131
    const int tt  = combo / 66;
    const int rem = combo % 66;
    const int mt  = rem / 6;
    const int ty  = rem % 6;
    const int tid = threadIdx.x;

    const float4 a = tok_type_emb[tt * H4 + tid];
    const float4 b = match_emb[mt * H4 + tid];
    const float4 c = type_emb[ty * H4 + tid];
    float4 r;
    r.x = a.x + b.x + c.x;
    r.y = a.y + b.y + c.y;
    r.z = a.z + b.z + c.z;
    r.w = a.w + b.w + c.w;
    g_comb[combo * H4 + tid] = r;
}

__global__ __launch_bounds__(TPB, 3)
void bert_emb_kernel(
    const int*    __restrict__ input_ids,       // [B,S]
    const int*    __restrict__ header_ids,      // [B,NC,MHL]
    const int*    __restrict__ token_type_ids,  // [B,S]
    const int*    __restrict__ match_type_ids,  // [B,S]
    const int*    __restrict__ type_idx,        // [B,S]
    const int*    __restrict__ col_pos,         // [B,NC]
    const int*    __restrict__ col_idx,         // [B,NC]
    const int*    __restrict__ header_len,      // [B,NC]
    const float4* __restrict__ word_emb,        // [VOCAB,H4]
    const float4* __restrict__ pos_emb,         // [MAX_POS,H4]
    const float4* __restrict__ ln_w,            // [H4]
    const float4* __restrict__ ln_b,            // [H4]
    float4*       __restrict__ out)             // [B,S,H4]
{
    const int tid  = threadIdx.x;
    const int warp = tid >> 5;
    const int lane = tid & 31;

    __shared__ float4 sgw[H4];
    __shared__ float4 sgb[H4];
    if (tid < H4) {
        sgw[tid] = ln_w[tid];
        sgb[tid] = ln_b[tid];
    }
    __syncthreads();

    // one warp == two consecutive rows (same batch since 2 | 512)
    const int rowA = (blockIdx.x * (TPB / 32) + warp) * 2;
    const int rowB = rowA + 1;
    const int b    = rowA >> 9;
    const int sA   = rowA & (SS - 1);
    const int sB   = sA + 1;

    // per-warp batch metadata (NC == 32)
    const int cp = col_pos[b * NC + lane];
    const int ci = col_idx[b * NC + lane];
    const int hl = header_len[b * NC + lane];

    // ---- column-scatter detection for both rows (register-only) ----
    const unsigned mmA = __ballot_sync(0xffffffffu, cp == sA);
    const unsigned mmB = __ballot_sync(0xffffffffu, cp == sB);
    int lenA = 0, cidxA = 0, lenB = 0, cidxB = 0;
    if (mmA) {
        const int c = __ffs(mmA) - 1;
        cidxA = __shfl_sync(0xffffffffu, ci, c);
        lenA  = __shfl_sync(0xffffffffu, hl, cidxA);
    }
    if (mmB) {
        const int c = __ffs(mmB) - 1;
        cidxB = __shfl_sync(0xffffffffu, ci, c);
        lenB  = __shfl_sync(0xffffffffu, hl, cidxB);
    }

    // small-table combo indices (L2 hits, independent)
    const int comboA = token_type_ids[rowA] * 66 + match_type_ids[rowA] * 6 + type_idx[rowA];
    const int comboB = token_type_ids[rowB] * 66 + match_type_ids[rowB] * 6 + type_idx[rowB];

    // ---- word gathers for both rows, issued back-to-back (MLP ~12) ----
    float4 vA[CPL], vB[CPL];
    {
        const size_t baseA = (size_t)input_ids[rowA] * H4 + lane;
        const size_t baseB = (size_t)input_ids[rowB] * H4 + lane;
        if (lenA == 0) {
            #pragma unroll
            for (int k = 0; k < CPL; ++k) vA[k] = word_emb[baseA + k * 32];
        }
        if (lenB == 0) {
            #pragma unroll
            for (int k = 0; k < CPL; ++k) vB[k] = word_emb[baseB + k * 32];
        }
    }

    // rare pooled path (~6% of rows)
    if (lenA > 0) {
        #pragma unroll
        for (int k = 0; k < CPL; ++k) vA[k] = make_float4(0.f, 0.f, 0.f, 0.f);
        const int* hids = header_ids + (b * NC + cidxA) * MHL;
        for (int l = 0; l < lenA; ++l) {
            const size_t base = (size_t)hids[l] * H4 + lane;
            #pragma unroll
            for (int k = 0; k < CPL; ++k) {
                const float4 w = word_emb[base + k * 32];
                vA[k].x += w.x; vA[k].y += w.y; vA[k].z += w.z; vA[k].w += w.w;
            }
        }
        const float inv = 1.0f / (float)lenA;
        #pragma unroll
        for (int k = 0; k < CPL; ++k) {
            vA[k].x *= inv; vA[k].y *= inv; vA[k].z *= inv; vA[k].w *= inv;
        }
    }
    if (lenB > 0) {
        #pragma unroll
        for (int k = 0; k < CPL; ++k) vB[k] = make_float4(0.f, 0.f, 0.f, 0.f);
        const int* hids = header_ids + (b * NC + cidxB) * MHL;
        for (int l = 0; l < lenB; ++l) {
            const size_t base = (size_t)hids[l] * H4 + lane;
            #pragma unroll
            for (int k = 0; k < CPL; ++k) {
                const float4 w = word_emb[base + k * 32];
                vB[k].x += w.x; vB[k].y += w.y; vB[k].z += w.z; vB[k].w += w.w;
            }
        }
        const float inv = 1.0f / (float)lenB;
        #pragma unroll
        for (int k = 0; k < CPL; ++k) {
            vB[k].x *= inv; vB[k].y *= inv; vB[k].z *= inv; vB[k].w *= inv;
        }
    }

    // ---- add positional + combined small-table for both rows ----
    {
        const size_t pA = (size_t)sA * H4 + lane;
        const size_t pB = (size_t)sB * H4 + lane;
        const size_t cA = (size_t)comboA * H4 + lane;
        const size_t cB = (size_t)comboB * H4 + lane;
        #pragma unroll
        for (int k = 0; k < CPL; ++k) {
            const float4 peA = pos_emb[pA + k * 32];
            const float4 cbA = g_comb[cA + k * 32];
            const float4 peB = pos_emb[pB + k * 32];
            const float4 cbB = g_comb[cB + k * 32];
            vA[k].x += peA.x + cbA.x;  vA[k].y += peA.y + cbA.y;
            vA[k].z += peA.z + cbA.z;  vA[k].w += peA.w + cbA.w;
            vB[k].x += peB.x + cbB.x;  vB[k].y += peB.y + cbB.y;
            vB[k].z += peB.z + cbB.z;  vB[k].w += peB.w + cbB.w;
        }
    }

    // ---- LayerNorm: two independent warp reduces (shuffle ILP=2) ----
    float sumA = 0.f, sqA = 0.f, sumB = 0.f, sqB = 0.f;
    #pragma unroll
    for (int k = 0; k < CPL; ++k) {
        sumA += vA[k].x + vA[k].y + vA[k].z + vA[k].w;
        sqA  += vA[k].x * vA[k].x + vA[k].y * vA[k].y
              + vA[k].z * vA[k].z + vA[k].w * vA[k].w;
        sumB += vB[k].x + vB[k].y + vB[k].z + vB[k].w;
        sqB  += vB[k].x * vB[k].x + vB[k].y * vB[k].y
              + vB[k].z * vB[k].z + vB[k].w * vB[k].w;
    }
    #pragma unroll
    for (int o = 16; o > 0; o >>= 1) {
        sumA += __shfl_xor_sync(0xffffffffu, sumA, o);
        sqA  += __shfl_xor_sync(0xffffffffu, sqA,  o);
        sumB += __shfl_xor_sync(0xffffffffu, sumB, o);
        sqB  += __shfl_xor_sync(0xffffffffu, sqB,  o);
    }
    const float meanA = sumA * (1.0f / HH);
    const float meanB = sumB * (1.0f / HH);
    float varA = fmaxf(sqA * (1.0f / HH) - meanA * meanA, 0.0f);
    float varB = fmaxf(sqB * (1.0f / HH) - meanB * meanB, 0.0f);
    const float rstdA = rsqrtf(varA + 1e-12f);
    const float rstdB = rsqrtf(varB + 1e-12f);

    // ---- scale, shift, store both rows ----
    float4* oA = out + (size_t)rowA * H4 + lane;
    float4* oB = out + (size_t)rowB * H4 + lane;
    #pragma unroll
    for (int k = 0; k < CPL; ++k) {
        const float4 gwv = sgw[lane + k * 32];
        const float4 gbv = sgb[lane + k * 32];
        float4 a, bo;
        a.x = (vA[k].x - meanA) * rstdA * gwv.x + gbv.x;
        a.y = (vA[k].y - meanA) * rstdA * gwv.y + gbv.y;
        a.z = (vA[k].z - meanA) * rstdA * gwv.z + gbv.z;
        a.w = (vA[k].w - meanA) * rstdA * gwv.w + gbv.w;
        bo.x = (vB[k].x - meanB) * rstdB * gwv.x + gbv.x;
        bo.y = (vB[k].y - meanB) * rstdB * gwv.y + gbv.y;
        bo.z = (vB[k].z - meanB) * rstdB * gwv.z + gbv.z;
        bo.w = (vB[k].w - meanB) * rstdB * gwv.w + gbv.w;
        __stcs(oA + k * 32, a);
        __stcs(oB + k * 32, bo);
    }
}

extern "C" void kernel_launch(void* const* d_in, const int* in_sizes, int n_in,
                              void* d_out, int out_size) {
    (void)in_sizes; (void)n_in; (void)out_size;
    const int*    input_ids       = (const int*)   d_in[0];
    const int*    header_ids      = (const int*)   d_in[1];
    const int*    token_type_ids  = (const int*)   d_in[2];
    const int*    match_type_ids  = (const int*)   d_in[3];
    const int*    type_idx        = (const int*)   d_in[4];
    const int*    col_pos         = (const int*)   d_in[5];
    const int*    col_idx         = (const int*)   d_in[6];
    const int*    header_len      = (const int*)   d_in[7];
    const float4* word_emb        = (const float4*)d_in[8];
    const float4* pos_emb         = (const float4*)d_in[9];
    const float4* tok_type_emb    = (const float4*)d_in[10];
    const float4* match_emb       = (const float4*)d_in[11];
    const float4* type_emb        = (const float4*)d_in[12];
    const float4* ln_w            = (const float4*)d_in[13];
    const float4* ln_b             = (const float4*)d_in[14];
    float4*       out             = (float4*)d_out;

    build_comb_kernel<<<NCOMB, 192>>>(tok_type_emb, match_emb, type_emb);

    // 16384 rows / (8 warps * 2 rows) = 1024 CTAs
    const int grid = (BB * SS) / ((TPB / 32) * 2);
    bert_emb_kernel<<<grid, TPB>>>(
        input_ids, header_ids, token_type_ids, match_type_ids, type_idx,
        col_pos, col_idx, header_len, word_emb, pos_emb, ln_w, ln_b, out);
}

// round 7
// speedup vs baseline: 1.2820x; 1.2820x over previous
#include <cuda_runtime.h>

#define BB   32
#define SS   512
#define HH   768
#define NC   32
#define MHL  16
#define H4   (HH / 4)       // 192
#define TPB  192            // thread tid owns column tid
#define RPC  4              // rows per CTA, fully interleaved
#define NCOMB (2 * 11 * 6)  // 132

__device__ float4 g_comb[NCOMB * H4];

__global__ __launch_bounds__(192)
void build_comb_kernel(const float4* __restrict__ tok_type_emb,
                       const float4* __restrict__ match_emb,
                       const float4* __restrict__ type_emb)
{
    const int combo = blockIdx.x;          // 0..131
    const int tt  = combo / 66;
    const int rem = combo % 66;
    const int mt  = rem / 6;
    const int ty  = rem % 6;
    const int tid = threadIdx.x;

    const float4 a = tok_type_emb[tt * H4 + tid];
    const float4 b = match_emb[mt * H4 + tid];
    const float4 c = type_emb[ty * H4 + tid];
    float4 r;
    r.x = a.x + b.x + c.x;
    r.y = a.y + b.y + c.y;
    r.z = a.z + b.z + c.z;
    r.w = a.w + b.w + c.w;
    g_comb[combo * H4 + tid] = r;
}

__global__ __launch_bounds__(TPB, 5)
void bert_emb_kernel(
    const int*    __restrict__ input_ids,       // [B,S]
    const int*    __restrict__ header_ids,      // [B,NC,MHL]
    const int*    __restrict__ token_type_ids,  // [B,S]
    const int*    __restrict__ match_type_ids,  // [B,S]
    const int*    __restrict__ type_idx,        // [B,S]
    const int*    __restrict__ col_pos,         // [B,NC]
    const int*    __restrict__ col_idx,         // [B,NC]
    const int*    __restrict__ header_len,      // [B,NC]
    const float4* __restrict__ word_emb,        // [VOCAB,H4]
    const float4* __restrict__ pos_emb,         // [MAX_POS,H4]
    const float4* __restrict__ ln_w,            // [H4]
    const float4* __restrict__ ln_b,            // [H4]
    float4*       __restrict__ out)             // [B,S,H4]
{
    const int tid  = threadIdx.x;
    const int warp = tid >> 5;
    const int lane = tid & 31;

    const int row0 = blockIdx.x * RPC;
    const int b    = row0 >> 9;
    const int s0   = row0 & (SS - 1);

    __shared__ int   sh_len[RPC];
    __shared__ int   sh_cidx[RPC];
    __shared__ float sh_sum[RPC][6];
    __shared__ float sh_sq[RPC][6];

    // ---- scatter detection: warp j handles row j ----
    if (warp < RPC) {
        const int cp = col_pos[b * NC + lane];
        const unsigned mm = __ballot_sync(0xffffffffu, cp == s0 + warp);
        if (lane == 0) {
            int len = 0, cidx = 0;
            if (mm) {
                const int c = __ffs(mm) - 1;
                cidx = col_idx[b * NC + c];
                len  = header_len[b * NC + cidx];
            }
            sh_len[warp]  = len;
            sh_cidx[warp] = cidx;
        }
    }

    // per-thread LN params (column tid, reused for all rows)
    const float4 gw = ln_w[tid];
    const float4 gb = ln_b[tid];

    __syncthreads();

    // ---- gather all 4 rows, fully interleaved ----
    float4 v[RPC];
    int combo[RPC];

    #pragma unroll
    for (int j = 0; j < RPC; ++j) {
        const int row = row0 + j;
        combo[j] = token_type_ids[row] * 66 + match_type_ids[row] * 6 + type_idx[row];
        const int len = sh_len[j];
        if (len == 0) {
            v[j] = word_emb[(size_t)input_ids[row] * H4 + tid];
        } else {
            float4 acc = make_float4(0.f, 0.f, 0.f, 0.f);
            const int* hids = header_ids + (b * NC + sh_cidx[j]) * MHL;
            for (int l = 0; l < len; ++l) {
                const float4 w = word_emb[(size_t)hids[l] * H4 + tid];
                acc.x += w.x; acc.y += w.y; acc.z += w.z; acc.w += w.w;
            }
            const float inv = 1.0f / (float)len;
            v[j].x = acc.x * inv; v[j].y = acc.y * inv;
            v[j].z = acc.z * inv; v[j].w = acc.w * inv;
        }
    }

    #pragma unroll
    for (int j = 0; j < RPC; ++j) {
        const float4 pe = pos_emb[(size_t)(s0 + j) * H4 + tid];
        const float4 cb = g_comb[(size_t)combo[j] * H4 + tid];
        v[j].x += pe.x + cb.x;
        v[j].y += pe.y + cb.y;
        v[j].z += pe.z + cb.z;
        v[j].w += pe.w + cb.w;
    }

    // ---- fused reduce for all 4 rows (shuffle ILP = 8) ----
    float sum[RPC], sq[RPC];
    #pragma unroll
    for (int j = 0; j < RPC; ++j) {
        sum[j] = v[j].x + v[j].y + v[j].z + v[j].w;
        sq[j]  = v[j].x * v[j].x + v[j].y * v[j].y
               + v[j].z * v[j].z + v[j].w * v[j].w;
    }
    #pragma unroll
    for (int o = 16; o > 0; o >>= 1) {
        #pragma unroll
        for (int j = 0; j < RPC; ++j) {
            sum[j] += __shfl_xor_sync(0xffffffffu, sum[j], o);
            sq[j]  += __shfl_xor_sync(0xffffffffu, sq[j],  o);
        }
    }
    if (lane == 0) {
        #pragma unroll
        for (int j = 0; j < RPC; ++j) {
            sh_sum[j][warp] = sum[j];
            sh_sq[j][warp]  = sq[j];
        }
    }
    __syncthreads();

    // every thread computes all 4 stats (broadcast LDS reads)
    float mean[RPC], rstd[RPC];
    #pragma unroll
    for (int j = 0; j < RPC; ++j) {
        float ts = 0.f, tq = 0.f;
        #pragma unroll
        for (int i = 0; i < 6; ++i) { ts += sh_sum[j][i]; tq += sh_sq[j][i]; }
        mean[j] = ts * (1.0f / HH);
        float var = fmaxf(tq * (1.0f / HH) - mean[j] * mean[j], 0.0f);
        rstd[j] = rsqrtf(var + 1e-12f);
    }

    // ---- scale, shift, store all 4 rows ----
    #pragma unroll
    for (int j = 0; j < RPC; ++j) {
        float4 o;
        o.x = (v[j].x - mean[j]) * rstd[j] * gw.x + gb.x;
        o.y = (v[j].y - mean[j]) * rstd[j] * gw.y + gb.y;
        o.z = (v[j].z - mean[j]) * rstd[j] * gw.z + gb.z;
        o.w = (v[j].w - mean[j]) * rstd[j] * gw.w + gb.w;
        __stcs(&out[(size_t)(row0 + j) * H4 + tid], o);
    }
}

extern "C" void kernel_launch(void* const* d_in, const int* in_sizes, int n_in,
                              void* d_out, int out_size) {
    (void)in_sizes; (void)n_in; (void)out_size;
    const int*    input_ids       = (const int*)   d_in[0];
    const int*    header_ids      = (const int*)   d_in[1];
    const int*    token_type_ids  = (const int*)   d_in[2];
    const int*    match_type_ids  = (const int*)   d_in[3];
    const int*    type_idx        = (const int*)   d_in[4];
    const int*    col_pos         = (const int*)   d_in[5];
    const int*    col_idx         = (const int*)   d_in[6];
    const int*    header_len      = (const int*)   d_in[7];
    const float4* word_emb        = (const float4*)d_in[8];
    const float4* pos_emb         = (const float4*)d_in[9];
    const float4* tok_type_emb    = (const float4*)d_in[10];
    const float4* match_emb       = (const float4*)d_in[11];
    const float4* type_emb        = (const float4*)d_in[12];
    const float4* ln_w            = (const float4*)d_in[13];
    const float4* ln_b            = (const float4*)d_in[14];
    float4*       out             = (float4*)d_out;

    build_comb_kernel<<<NCOMB, 192>>>(tok_type_emb, match_emb, type_emb);

    const int grid = (BB * SS) / RPC;     // 4096 CTAs
    bert_emb_kernel<<<grid, TPB>>>(
        input_ids, header_ids, token_type_ids, match_type_ids, type_idx,
        col_pos, col_idx, header_len, word_emb, pos_emb, ln_w, ln_b, out);
}